// round 1
// baseline (speedup 1.0000x reference)
#include <cuda_runtime.h>

// ---------------------------------------------------------------------------
// AutoregressiveEncoder: persistent cooperative kernel.
//   B=32 T=512 IN=OUT=512 LH=512, 2 layers x 2 directions = 4 LSTM cells/step
//   Per step: stage L0 (cells 0,1) -> barrier -> L1 (cells 2,3) -> barrier ->
//             FC head (512x1024) -> barrier.
//   128 CTAs x 256 threads. lanes = batch. warp = one hidden unit (4 gates).
//   Activations are feature-major [k][b], float4-packed over k, staged in SMEM.
// ---------------------------------------------------------------------------

#define BATCH  32
#define SEQT   512
#define DIN    512
#define DOUT   512
#define DLH    512
#define NCELL  4
#define K4     128                      // 512/4 float4 rows per 512-wide segment
#define SEGSZ  (K4 * BATCH)             // 4096 float4 per segment
#define NTHR   256
#define NCTA   128
#define SMEM_BYTES (3 * SEGSZ * sizeof(float4))   // 196608 B

// Global scratch (static __device__ arrays: allocation-free).
__device__ float4 g_xT[(size_t)SEQT * SEGSZ];      // transposed input  [t][k4][b]
__device__ float4 g_hT[2 * NCELL * SEGSZ];         // h, double buffered by parity
__device__ float4 g_prevT[SEGSZ];                  // previous prediction (transposed)
__device__ float  g_cT[NCELL * DLH * BATCH];       // cell state [cell][j][b]
__device__ unsigned g_arrive  = 0;                 // monotonic ticket barrier
__device__ unsigned g_release = 0;

// Grid barrier: monotonic ticket/release counters, wrap-safe, cross-launch-safe.
// Valid because gridDim.x (128) <= #SMs and 1 CTA/SM (196KB smem) => all resident.
__device__ __forceinline__ void gridbar() {
    __syncthreads();
    if (threadIdx.x == 0) {
        __threadfence();
        const unsigned nb = gridDim.x;
        unsigned ticket = atomicAdd(&g_arrive, 1u);
        if (ticket % nb == nb - 1u) {
            atomicAdd(&g_release, nb);          // release this round
        } else {
            volatile unsigned* rel = &g_release;
            while ((int)(*rel - ticket) <= 0) __nanosleep(64);
        }
        __threadfence();
    }
    __syncthreads();
}

__device__ __forceinline__ float sigf(float v) { return 1.0f / (1.0f + expf(-v)); }

#define DOT4ACC(acc, w, v) \
    acc = fmaf((w).x,(v).x, fmaf((w).y,(v).y, fmaf((w).z,(v).z, fmaf((w).w,(v).w,(acc)))))

// One LSTM cell phase for this CTA's 8 hidden units (one per warp).
// seg0/seg1 pair with Wih columns [0:512)/[512:1024); seg2 pairs with Whh.
__device__ __forceinline__ void lstm_phase(
    float4* sAct,
    const float4* __restrict__ s0, const float4* __restrict__ s1,
    const float4* __restrict__ s2,
    const float* __restrict__ Wih_c, const float* __restrict__ Whh_c,
    const float* __restrict__ bih_c, const float* __restrict__ bhh_c,
    int cell, int pnew, int j)
{
    const int tid  = threadIdx.x;
    const int lane = tid & 31;

    // Stage the 3 activation segments (x|prev|h or h0|h1|h) into SMEM.
    for (int i = tid; i < SEGSZ; i += NTHR) {
        sAct[i]           = s0[i];
        sAct[SEGSZ + i]   = s1[i];
        sAct[2*SEGSZ + i] = s2[i];
    }
    __syncthreads();

    const float4* wa0 = (const float4*)(Wih_c + (size_t)(j         ) * 1024);
    const float4* wa1 = (const float4*)(Wih_c + (size_t)(j +  512) * 1024);
    const float4* wa2 = (const float4*)(Wih_c + (size_t)(j + 1024) * 1024);
    const float4* wa3 = (const float4*)(Wih_c + (size_t)(j + 1536) * 1024);
    const float4* wh0 = (const float4*)(Whh_c + (size_t)(j         ) * 512);
    const float4* wh1 = (const float4*)(Whh_c + (size_t)(j +  512) * 512);
    const float4* wh2 = (const float4*)(Whh_c + (size_t)(j + 1024) * 512);
    const float4* wh3 = (const float4*)(Whh_c + (size_t)(j + 1536) * 512);

    float a0 = 0.f, a1 = 0.f, a2 = 0.f, a3 = 0.f;

    #pragma unroll 4
    for (int k = 0; k < K4; ++k) {                 // segment 0: Wih[:, 0:512)
        float4 v = sAct[k * BATCH + lane];
        float4 w;
        w = wa0[k]; DOT4ACC(a0, w, v);
        w = wa1[k]; DOT4ACC(a1, w, v);
        w = wa2[k]; DOT4ACC(a2, w, v);
        w = wa3[k]; DOT4ACC(a3, w, v);
    }
    #pragma unroll 4
    for (int k = 0; k < K4; ++k) {                 // segment 1: Wih[:, 512:1024)
        float4 v = sAct[SEGSZ + k * BATCH + lane];
        float4 w;
        w = wa0[K4 + k]; DOT4ACC(a0, w, v);
        w = wa1[K4 + k]; DOT4ACC(a1, w, v);
        w = wa2[K4 + k]; DOT4ACC(a2, w, v);
        w = wa3[K4 + k]; DOT4ACC(a3, w, v);
    }
    #pragma unroll 4
    for (int k = 0; k < K4; ++k) {                 // segment 2: Whh
        float4 v = sAct[2*SEGSZ + k * BATCH + lane];
        float4 w;
        w = wh0[k]; DOT4ACC(a0, w, v);
        w = wh1[k]; DOT4ACC(a1, w, v);
        w = wh2[k]; DOT4ACC(a2, w, v);
        w = wh3[k]; DOT4ACC(a3, w, v);
    }

    a0 += __ldg(bih_c + j)        + __ldg(bhh_c + j);
    a1 += __ldg(bih_c + j +  512) + __ldg(bhh_c + j +  512);
    a2 += __ldg(bih_c + j + 1024) + __ldg(bhh_c + j + 1024);
    a3 += __ldg(bih_c + j + 1536) + __ldg(bhh_c + j + 1536);

    // PyTorch gate order: i, f, g, o
    float ig = sigf(a0), fg = sigf(a1), gv = tanhf(a2), og = sigf(a3);
    float* cp = g_cT + ((size_t)cell * DLH + j) * BATCH + lane;
    float cc  = fg * (*cp) + ig * gv;
    *cp = cc;
    float hv = og * tanhf(cc);
    ((float*)g_hT)[ ((((size_t)pnew * NCELL + cell) * K4 + (j >> 2)) * BATCH + lane) * 4 + (j & 3) ] = hv;
}

extern "C" __global__ void __launch_bounds__(NTHR, 1)
ar_encoder_kernel(const float* __restrict__ x,      // [B,T,IN]
                  const float* __restrict__ Wih,    // [2][2][2048][1024]
                  const float* __restrict__ Whh,    // [2][2][2048][512]
                  const float* __restrict__ bih,    // [2][2][2048]
                  const float* __restrict__ bhh,    // [2][2][2048]
                  const float* __restrict__ Wfc,    // [512][1024]
                  const float* __restrict__ bfc,    // [512]
                  float* __restrict__ out)          // outputs | h_n | c_n
{
    extern __shared__ float4 sAct[];                // [3][K4][BATCH]
    const int tid  = threadIdx.x;
    const int cta  = blockIdx.x;
    const int lane = tid & 31;
    const int wrp  = tid >> 5;
    const int gsz  = gridDim.x * NTHR;
    const int gtid = cta * NTHR + tid;

    // ---- prologue: transpose input to [t][k4][b] float4; zero states ----
    for (size_t i = gtid; i < (size_t)BATCH * SEQT * K4; i += gsz) {
        int    k4 = (int)(i % K4);
        size_t bt = i / K4;
        int    t  = (int)(bt % SEQT);
        int    b  = (int)(bt / SEQT);
        float4 v  = *(const float4*)(x + ((size_t)b * SEQT + t) * DIN + 4 * k4);
        g_xT[((size_t)t * K4 + k4) * BATCH + b] = v;
    }
    for (int i = gtid; i < 2 * NCELL * SEGSZ; i += gsz) g_hT[i]    = make_float4(0.f,0.f,0.f,0.f);
    for (int i = gtid; i < SEGSZ;             i += gsz) g_prevT[i] = make_float4(0.f,0.f,0.f,0.f);
    for (int i = gtid; i < NCELL * DLH * BATCH; i += gsz) g_cT[i]  = 0.f;
    gridbar();

    const int d     = cta >> 6;            // direction group: 0 = fwd, 1 = bwd
    const int jbase = (cta & 63) * 8;
    const int j     = jbase + wrp;         // this warp's hidden unit

    for (int t = 0; t < SEQT; ++t) {
        const int pold = t & 1, pnew = pold ^ 1;

        // ---- layer 0 (cells 0,1): input = [x_t | prev | h_{t-1}] ----
        {
            const int cell = d;
            lstm_phase(sAct,
                       g_xT + (size_t)t * SEGSZ,
                       g_prevT,
                       g_hT + (size_t)(pold * NCELL + cell) * SEGSZ,
                       Wih + (size_t)cell * 2048 * 1024,
                       Whh + (size_t)cell * 2048 * 512,
                       bih + (size_t)cell * 2048,
                       bhh + (size_t)cell * 2048,
                       cell, pnew, j);
            gridbar();
        }
        // ---- layer 1 (cells 2,3): input = [h0_new | h1_new | h_{t-1}] ----
        {
            const int cell = 2 + d;
            lstm_phase(sAct,
                       g_hT + (size_t)(pnew * NCELL + 0) * SEGSZ,
                       g_hT + (size_t)(pnew * NCELL + 1) * SEGSZ,
                       g_hT + (size_t)(pold * NCELL + cell) * SEGSZ,
                       Wih + (size_t)cell * 2048 * 1024,
                       Whh + (size_t)cell * 2048 * 512,
                       bih + (size_t)cell * 2048,
                       bhh + (size_t)cell * 2048,
                       cell, pnew, j);
            gridbar();
        }
        // ---- FC head: pred = [h2_new | h3_new] @ Wfc^T + bfc ----
        {
            const float4* s0 = g_hT + (size_t)(pnew * NCELL + 2) * SEGSZ;
            const float4* s1 = g_hT + (size_t)(pnew * NCELL + 3) * SEGSZ;
            for (int i = tid; i < SEGSZ; i += NTHR) {
                sAct[i]         = s0[i];
                sAct[SEGSZ + i] = s1[i];
            }
            __syncthreads();
            if (wrp < 4) {
                const int row = cta * 4 + wrp;
                const float4* wf = (const float4*)(Wfc + (size_t)row * 1024);
                float s = __ldg(bfc + row);
                #pragma unroll 4
                for (int k = 0; k < K4; ++k) {
                    float4 v = sAct[k * BATCH + lane];
                    float4 w = wf[k];
                    DOT4ACC(s, w, v);
                }
                #pragma unroll 4
                for (int k = 0; k < K4; ++k) {
                    float4 v = sAct[SEGSZ + k * BATCH + lane];
                    float4 w = wf[K4 + k];
                    DOT4ACC(s, w, v);
                }
                out[((size_t)lane * SEQT + t) * DOUT + row] = s;   // outputs[b][t][row]
                ((float*)g_prevT)[((size_t)(row >> 2) * BATCH + lane) * 4 + (row & 3)] = s;
            }
            gridbar();
        }
    }

    // ---- epilogue: h_n, c_n. Final state parity = (511&1)^1 = 0. ----
    const size_t HN = (size_t)BATCH * SEQT * DOUT;
    for (int i = gtid; i < NCELL * BATCH * DLH; i += gsz) {
        int jj   = i % DLH;
        int b    = (i / DLH) % BATCH;
        int cell = i / (DLH * BATCH);
        float hv = ((const float*)g_hT)[ (((size_t)cell * K4 + (jj >> 2)) * BATCH + b) * 4 + (jj & 3) ];
        out[HN + i] = hv;
        out[HN + (size_t)NCELL * BATCH * DLH + i] = g_cT[((size_t)cell * DLH + jj) * BATCH + b];
    }
}

extern "C" void kernel_launch(void* const* d_in, const int* in_sizes, int n_in,
                              void* d_out, int out_size) {
    (void)in_sizes; (void)n_in; (void)out_size;
    const float* x   = (const float*)d_in[0];
    // d_in[1] = input_lengths (all == T; reference ignores them)
    const float* Wih = (const float*)d_in[2];
    const float* Whh = (const float*)d_in[3];
    const float* bih = (const float*)d_in[4];
    const float* bhh = (const float*)d_in[5];
    const float* Wfc = (const float*)d_in[6];
    const float* bfc = (const float*)d_in[7];

    cudaFuncSetAttribute(ar_encoder_kernel,
                         cudaFuncAttributeMaxDynamicSharedMemorySize, SMEM_BYTES);
    ar_encoder_kernel<<<NCTA, NTHR, SMEM_BYTES>>>(x, Wih, Whh, bih, bhh, Wfc, bfc,
                                                  (float*)d_out);
}

// round 2
// speedup vs baseline: 3.8804x; 3.8804x over previous
#include <cuda_runtime.h>
#include <cuda_bf16.h>

typedef unsigned int uint;

#define NTHR 256
#define NCTA 128

// Fragment-buffer geometry
#define CHUNK_U4   6144u        // per (cell,ublk,mtile): 96 ksteps * 2 splits * 32 lanes (uint4 each)
#define SEG_U4     4096u        // one B segment (K=512): 4 ntiles * 32 ksteps * 32 lanes
#define FCCHUNK_U4 4096u        // FC A chunk: 64 ksteps * 2 splits * 32 lanes

// Static device scratch (allocation-free)
__device__ uint4 g_awfrag[512u * CHUNK_U4];     // LSTM weight A-fragments (hi|lo)  ~50MB
__device__ uint4 g_afcfrag[32u * FCCHUNK_U4];   // FC weight A-fragments            ~2MB
__device__ uint4 g_xfrag[512ull * SEG_U4];      // input x B-fragments, all t       ~32MB
__device__ uint4 g_hfrag[8u * SEG_U4];          // h B-fragments [parity][cell]     512KB
__device__ uint4 g_pfrag[SEG_U4];               // prev-pred B-fragments            64KB
__device__ unsigned g_arrive  = 0;
__device__ unsigned g_release = 0;

// ---------------- grid barrier (monotonic ticket; 128 CTAs <= #SMs) ----------
__device__ __forceinline__ void gridbar() {
    __syncthreads();
    if (threadIdx.x == 0) {
        __threadfence();
        const unsigned nb = gridDim.x;
        unsigned ticket = atomicAdd(&g_arrive, 1u);
        if (ticket % nb == nb - 1u) {
            atomicAdd(&g_release, nb);
        } else {
            volatile unsigned* rel = &g_release;
            while ((int)(*rel - ticket) <= 0) __nanosleep(32);
        }
        __threadfence();
    }
    __syncthreads();
}

__device__ __forceinline__ float sigf(float v) { return 1.0f / (1.0f + expf(-v)); }

// ---------------- bf16 split helpers ----------------------------------------
__device__ __forceinline__ void split_pair(float a, float b, uint& hi, uint& lo) {
    __nv_bfloat16 ha = __float2bfloat16(a), hb = __float2bfloat16(b);
    float ra = a - __bfloat162float(ha);
    float rb = b - __bfloat162float(hb);
    __nv_bfloat16 la = __float2bfloat16(ra), lb = __float2bfloat16(rb);
    hi = (uint)__bfloat16_as_ushort(ha) | ((uint)__bfloat16_as_ushort(hb) << 16);
    lo = (uint)__bfloat16_as_ushort(la) | ((uint)__bfloat16_as_ushort(lb) << 16);
}

// Write one activation value (k,n) into B-fragment slots (hi and lo halves).
__device__ __forceinline__ void write_bfrag(uint4* base, int k, int n, float v) {
    __nv_bfloat16 hi = __float2bfloat16(v);
    float rem = v - __bfloat162float(hi);
    __nv_bfloat16 lo = __float2bfloat16(rem);
    int ks = k >> 4, kk = k & 15, nt = n >> 3;
    int tp  = ((n & 7) << 2) | ((kk >> 1) & 3);
    int reg = kk >> 3;          // b0 / b1
    int half = kk & 1;
    char* p = (char*)(base + ((size_t)(nt * 32 + ks) * 32 + tp));
    *(__nv_bfloat16*)(p + reg * 4 + half * 2)     = hi;   // hi at bytes [0,8)
    *(__nv_bfloat16*)(p + 8 + reg * 4 + half * 2) = lo;   // lo at bytes [8,16)
}

// ---------------- mma.sync m16n8k16 bf16 -> fp32 -----------------------------
struct Acc { float x, y, z, w; };

__device__ __forceinline__ void mma_bf16(Acc& c, uint4 a, uint b0, uint b1) {
    asm volatile(
        "mma.sync.aligned.m16n8k16.row.col.f32.bf16.bf16.f32 "
        "{%0,%1,%2,%3}, {%4,%5,%6,%7}, {%8,%9}, {%0,%1,%2,%3};"
        : "+f"(c.x), "+f"(c.y), "+f"(c.z), "+f"(c.w)
        : "r"(a.x), "r"(a.y), "r"(a.z), "r"(a.w), "r"(b0), "r"(b1));
}

// One K=512 segment: 32 ksteps, 3 split-MMAs each, 3 independent accumulators.
// A: + lane already applied; layout (kstep*2+split)*32. B: + ntile*1024 + lane.
__device__ __forceinline__ void mma_seg(const uint4* __restrict__ A,
                                        const uint4* __restrict__ B,
                                        Acc& cA, Acc& cB, Acc& cC) {
    #pragma unroll 8
    for (int ks = 0; ks < 32; ++ks) {
        uint4 bv = __ldg(B + ks * 32);
        uint4 ah = __ldg(A + ks * 64);
        uint4 al = __ldg(A + ks * 64 + 32);
        mma_bf16(cA, ah, bv.x, bv.y);   // hi * hi
        mma_bf16(cB, ah, bv.z, bv.w);   // hi * lo
        mma_bf16(cC, al, bv.x, bv.y);   // lo * hi
    }
}

// Store warp C-fragments to SMEM gate buffer, then LSTM pointwise update.
__device__ __forceinline__ void lstm_pointwise(
    float* sG, Acc cA, Acc cB, Acc cC,
    int mtile, int ntile, int lane, int tid,
    const float* __restrict__ bihc, const float* __restrict__ bhhc,
    float& creg, float& hreg, uint4* hout, int j0)
{
    float c0 = cA.x + cB.x + cC.x;
    float c1 = cA.y + cB.y + cC.y;
    float c2 = cA.z + cB.z + cC.z;
    float c3 = cA.w + cB.w + cC.w;
    int gid = lane >> 2, tig = lane & 3;
    int m0 = mtile * 16 + gid;
    int n0 = ntile * 8 + tig * 2;
    sG[m0 * 33 + n0]       = c0;
    sG[m0 * 33 + n0 + 1]   = c1;
    sG[(m0+8) * 33 + n0]   = c2;
    sG[(m0+8) * 33 + n0+1] = c3;
    __syncthreads();
    int ul = tid >> 5, b = tid & 31;
    int j = j0 + ul;
    float gi = sG[(ul*4+0)*33 + b] + __ldg(bihc + j)        + __ldg(bhhc + j);
    float gf = sG[(ul*4+1)*33 + b] + __ldg(bihc + j +  512) + __ldg(bhhc + j +  512);
    float gg = sG[(ul*4+2)*33 + b] + __ldg(bihc + j + 1024) + __ldg(bhhc + j + 1024);
    float go = sG[(ul*4+3)*33 + b] + __ldg(bihc + j + 1536) + __ldg(bhhc + j + 1536);
    float cc = sigf(gf) * creg + sigf(gi) * tanhf(gg);
    creg = cc;
    hreg = sigf(go) * tanhf(cc);
    write_bfrag(hout, j, b, hreg);
}

// -----------------------------------------------------------------------------
extern "C" __global__ void __launch_bounds__(NTHR, 1)
ar_encoder_mma(const float* __restrict__ x,     // [B,T,IN] = [32,512,512]
               const float* __restrict__ Wih,   // [4][2048][1024]
               const float* __restrict__ Whh,   // [4][2048][512]
               const float* __restrict__ bih,   // [4][2048]
               const float* __restrict__ bhh,   // [4][2048]
               const float* __restrict__ Wfc,   // [512][1024]
               const float* __restrict__ bfc,   // [512]
               float* __restrict__ out)
{
    __shared__ float sG[32 * 33];
    const int tid  = threadIdx.x;
    const int cta  = blockIdx.x;
    const int lane = tid & 31;
    const int wrp  = tid >> 5;
    const int gsz  = NCTA * NTHR;
    const int gtid = cta * NTHR + tid;

    // ================= prologue: build fragment buffers ======================
    // (1) LSTM weights -> A fragments (hi & lo), gate-interleaved rows
    for (uint i = gtid; i < 4u * 2048u * 768u; i += gsz) {
        int kp   = (int)(i % 768u);
        int row  = (int)((i / 768u) & 2047u);
        int cell = (int)(i / (768u * 2048u));
        int k = kp * 2;
        float w0, w1;
        if (k < 1024) {
            const float* p = Wih + ((size_t)cell * 2048 + row) * 1024 + k;
            w0 = p[0]; w1 = p[1];
        } else {
            const float* p = Whh + ((size_t)cell * 2048 + row) * 512 + (k - 1024);
            w0 = p[0]; w1 = p[1];
        }
        uint hi, lo; split_pair(w0, w1, hi, lo);
        int gate = row >> 9, u = row & 511, ublk = u >> 3, ul = u & 7;
        int m = ul * 4 + gate, mtile = m >> 4, mrow = m & 15;
        int kstep = k >> 4, kk = k & 15;
        int tp  = ((mrow & 7) << 2) | ((kk >> 1) & 3);
        int reg = (mrow >> 3) | ((kk >> 3) << 1);
        size_t chunk = (size_t)(cell * 64 + ublk) * 2 + mtile;
        uint* dh = (uint*)(g_awfrag + chunk * CHUNK_U4 + (size_t)kstep * 64 + tp);
        dh[reg] = hi;
        uint* dl = (uint*)(g_awfrag + chunk * CHUNK_U4 + (size_t)kstep * 64 + 32 + tp);
        dl[reg] = lo;
    }
    // (2) FC weights -> A fragments
    for (uint i = gtid; i < 512u * 512u; i += gsz) {
        int kp = (int)(i & 511u), row = (int)(i >> 9);
        int k = kp * 2;
        const float* p = Wfc + ((size_t)row << 10) + k;
        uint hi, lo; split_pair(p[0], p[1], hi, lo);
        int rowblk = row >> 4, mrow = row & 15;
        int kstep = k >> 4, kk = k & 15;
        int tp  = ((mrow & 7) << 2) | ((kk >> 1) & 3);
        int reg = (mrow >> 3) | ((kk >> 3) << 1);
        uint* dh = (uint*)(g_afcfrag + (size_t)rowblk * FCCHUNK_U4 + (size_t)kstep * 64 + tp);
        dh[reg] = hi;
        uint* dl = (uint*)(g_afcfrag + (size_t)rowblk * FCCHUNK_U4 + (size_t)kstep * 64 + 32 + tp);
        dl[reg] = lo;
    }
    // (3) input x -> B fragments for all 512 steps (one uint4 slot per thread-iter)
    for (size_t s = gtid; s < 512ull * SEG_U4; s += gsz) {
        int ln = (int)(s & 31), ks = (int)((s >> 5) & 31), nt = (int)((s >> 10) & 3);
        int t  = (int)(s >> 12);
        int tig = ln & 3, gid = ln >> 2;
        int n = nt * 8 + gid, k0 = ks * 16 + tig * 2;
        const float* xp = x + ((size_t)n * 512 + t) * 512 + k0;
        float a0 = xp[0], a1 = xp[1], a2 = xp[8], a3 = xp[9];
        uint4 v;
        split_pair(a0, a1, v.x, v.z);
        split_pair(a2, a3, v.y, v.w);
        g_xfrag[s] = v;
    }
    // (4) zero parity-0 h fragments + prev fragments
    {
        uint4 z = make_uint4(0, 0, 0, 0);
        for (uint i = gtid; i < 5u * SEG_U4; i += gsz) {
            if (i < 4u * SEG_U4) g_hfrag[i] = z;
            else                 g_pfrag[i - 4u * SEG_U4] = z;
        }
    }
    gridbar();

    // ================= main autoregressive loop ==============================
    const int d     = cta >> 6;          // direction 0/1
    const int ublk  = cta & 63;          // 8-unit block
    const int j0    = ublk * 8;
    const int mtile = wrp >> 2;
    const int ntile = wrp & 3;
    float creg0 = 0.f, hreg0 = 0.f, creg1 = 0.f, hreg1 = 0.f;

    const size_t chunk0 = ((size_t)((0 + d) * 64 + ublk) * 2 + mtile) * CHUNK_U4;
    const size_t chunk1 = ((size_t)((2 + d) * 64 + ublk) * 2 + mtile) * CHUNK_U4;
    const int boff = ntile * 1024 + lane;

    for (int t = 0; t < 512; ++t) {
        const int pold = t & 1, pnew = pold ^ 1;

        // ---- layer 0 (cell = d): K = [x_t | prev | h_old(cell)] ----
        {
            const int cell = d;
            const uint4* A  = g_awfrag + chunk0 + lane;
            const uint4* B0 = g_xfrag + (size_t)t * SEG_U4 + boff;
            const uint4* B1 = g_pfrag + boff;
            const uint4* B2 = g_hfrag + (size_t)(pold * 4 + cell) * SEG_U4 + boff;
            Acc cA = {0,0,0,0}, cB = {0,0,0,0}, cC = {0,0,0,0};
            mma_seg(A,        B0, cA, cB, cC);
            mma_seg(A + 2048, B1, cA, cB, cC);
            mma_seg(A + 4096, B2, cA, cB, cC);
            lstm_pointwise(sG, cA, cB, cC, mtile, ntile, lane, tid,
                           bih + (size_t)cell * 2048, bhh + (size_t)cell * 2048,
                           creg0, hreg0,
                           g_hfrag + (size_t)(pnew * 4 + cell) * SEG_U4, j0);
        }
        gridbar();

        // ---- layer 1 (cell = 2+d): K = [h0_new | h1_new | h_old(cell)] ----
        {
            const int cell = 2 + d;
            const uint4* A  = g_awfrag + chunk1 + lane;
            const uint4* B0 = g_hfrag + (size_t)(pnew * 4 + 0) * SEG_U4 + boff;
            const uint4* B1 = g_hfrag + (size_t)(pnew * 4 + 1) * SEG_U4 + boff;
            const uint4* B2 = g_hfrag + (size_t)(pold * 4 + cell) * SEG_U4 + boff;
            Acc cA = {0,0,0,0}, cB = {0,0,0,0}, cC = {0,0,0,0};
            mma_seg(A,        B0, cA, cB, cC);
            mma_seg(A + 2048, B1, cA, cB, cC);
            mma_seg(A + 4096, B2, cA, cB, cC);
            lstm_pointwise(sG, cA, cB, cC, mtile, ntile, lane, tid,
                           bih + (size_t)cell * 2048, bhh + (size_t)cell * 2048,
                           creg1, hreg1,
                           g_hfrag + (size_t)(pnew * 4 + cell) * SEG_U4, j0);
        }
        gridbar();

        // ---- FC head on CTAs 0..31: pred = [h2_new | h3_new] @ Wfc^T + bfc ----
        if (cta < 32) {
            if (wrp < 4) {
                const uint4* A  = g_afcfrag + (size_t)cta * FCCHUNK_U4 + lane;
                const uint4* B2 = g_hfrag + (size_t)(pnew * 4 + 2) * SEG_U4 + wrp * 1024 + lane;
                const uint4* B3 = g_hfrag + (size_t)(pnew * 4 + 3) * SEG_U4 + wrp * 1024 + lane;
                Acc cA = {0,0,0,0}, cB = {0,0,0,0}, cC = {0,0,0,0};
                mma_seg(A,        B2, cA, cB, cC);
                mma_seg(A + 2048, B3, cA, cB, cC);
                float c0 = cA.x + cB.x + cC.x;
                float c1 = cA.y + cB.y + cC.y;
                float c2 = cA.z + cB.z + cC.z;
                float c3 = cA.w + cB.w + cC.w;
                int gid = lane >> 2, tig = lane & 3;
                int n0 = wrp * 8 + tig * 2;
                sG[gid * 33 + n0]       = c0;
                sG[gid * 33 + n0 + 1]   = c1;
                sG[(gid+8) * 33 + n0]   = c2;
                sG[(gid+8) * 33 + n0+1] = c3;
            }
            __syncthreads();
            int r = tid >> 5, b = tid & 31;
            #pragma unroll
            for (int hh = 0; hh < 2; ++hh) {
                int rr  = r + hh * 8;
                int row = cta * 16 + rr;
                float v = sG[rr * 33 + b] + __ldg(bfc + row);
                out[((size_t)b * 512 + t) * 512 + row] = v;
                write_bfrag(g_pfrag, row, b, v);
            }
        }
        gridbar();
    }

    // ================= epilogue: h_n, c_n from registers =====================
    {
        const size_t HN = 8388608ull;             // 32*512*512
        const size_t CN = HN + 65536ull;          // + 4*32*512
        int ul = tid >> 5, b = tid & 31;
        int j = j0 + ul;
        int cell0 = d, cell1 = 2 + d;
        out[HN + ((size_t)(cell0 * 32 + b)) * 512 + j] = hreg0;
        out[HN + ((size_t)(cell1 * 32 + b)) * 512 + j] = hreg1;
        out[CN + ((size_t)(cell0 * 32 + b)) * 512 + j] = creg0;
        out[CN + ((size_t)(cell1 * 32 + b)) * 512 + j] = creg1;
    }
}

extern "C" void kernel_launch(void* const* d_in, const int* in_sizes, int n_in,
                              void* d_out, int out_size) {
    (void)in_sizes; (void)n_in; (void)out_size;
    const float* x   = (const float*)d_in[0];
    const float* Wih = (const float*)d_in[2];
    const float* Whh = (const float*)d_in[3];
    const float* bih = (const float*)d_in[4];
    const float* bhh = (const float*)d_in[5];
    const float* Wfc = (const float*)d_in[6];
    const float* bfc = (const float*)d_in[7];
    ar_encoder_mma<<<NCTA, NTHR>>>(x, Wih, Whh, bih, bhh, Wfc, bfc, (float*)d_out);
}